// round 1
// baseline (speedup 1.0000x reference)
#include <cuda_runtime.h>
#include <math.h>
#include <stdint.h>

#define BATCH 512
#define HIDN  196
#define RECN  488
#define G3N   1464      // 3*RECN
#define NCN   35
#define TN    120
#define BH    (BATCH*RECN)
#define BG    (BATCH*G3N)

// ---------------- scratch (static device allocations) ----------------
__device__ float g_z1 [BATCH*HIDN];
__device__ float g_z2 [BATCH*HIDN];
__device__ float g_xg0[BATCH*G3N];
__device__ float g_X0 [(size_t)TN*BATCH*RECN];     // GRU0 outputs, [t][b][488]
__device__ float g_XG1[(size_t)TN*BATCH*G3N];      // GRU1 input gates, [t][b][1464]
__device__ float g_X1 [(size_t)TN*BATCH*RECN];     // GRU1 outputs
__device__ float g_XGc[(size_t)TN*BATCH*3*NCN];    // cell input gates, [t][b][105]
__device__ float g_WtD0[HIDN*HIDN];
__device__ float g_WtD1[HIDN*HIDN];
__device__ float g_Wt0x[HIDN*G3N];
__device__ float g_Wt0h[RECN*G3N];
__device__ float g_Wt1x[RECN*G3N];
__device__ float g_Wt1h[RECN*G3N];
__device__ float g_Wtc [RECN*3*NCN];

// ---------------- transpose: in[R][C] -> out[C][R] ----------------
__global__ void transpose_k(const float* __restrict__ in, float* __restrict__ out,
                            int R, int C) {
    __shared__ float tile[32][33];
    int c0 = blockIdx.x * 32, r0 = blockIdx.y * 32;
    int tx = threadIdx.x, ty = threadIdx.y;      // block (32,8)
    for (int i = ty; i < 32; i += 8) {
        int r = r0 + i, c = c0 + tx;
        tile[i][tx] = (r < R && c < C) ? in[(size_t)r * C + c] : 0.f;
    }
    __syncthreads();
    for (int i = ty; i < 32; i += 8) {
        int r = r0 + tx, c = c0 + i;
        if (c < C && r < R) out[(size_t)c * R + r] = tile[tx][i];
    }
}

// ---------------- generic 128x128 tiled SGEMM: C = A[MxK] @ Bt[KxN] ----------------
// mode 0: C=acc   mode 1: C=acc+bias   mode 2: C=gamma*((acc+bias)*invs)+beta (fused BN)
__global__ __launch_bounds__(256)
void gemm128(const float* __restrict__ A, const float* __restrict__ Bt,
             const float* __restrict__ bias, const float* __restrict__ gamma,
             const float* __restrict__ beta, float* __restrict__ C,
             int M, int N, int K, int mode) {
    __shared__ float As[16][132];
    __shared__ float Bs[16][128];
    int tid = threadIdx.x;
    int tx = tid & 15, ty = tid >> 4;
    int rowBase = blockIdx.y * 128, colBase = blockIdx.x * 128;
    float acc[8][8];
#pragma unroll
    for (int i = 0; i < 8; i++)
#pragma unroll
        for (int j = 0; j < 8; j++) acc[i][j] = 0.f;

    for (int k0 = 0; k0 < K; k0 += 16) {
        {   // A tile: 128 x 16
            int kk = tid & 15, m0 = tid >> 4;
#pragma unroll
            for (int l = 0; l < 8; l++) {
                int m = m0 + l * 16;
                float v = 0.f;
                if (k0 + kk < K) v = A[(size_t)(rowBase + m) * K + k0 + kk];
                As[kk][m] = v;
            }
        }
        {   // B tile: 16 x 128
            int c = tid & 127, kb = tid >> 7;
#pragma unroll
            for (int l = 0; l < 8; l++) {
                int kk = kb + l * 2;
                float v = 0.f;
                if ((k0 + kk) < K && (colBase + c) < N)
                    v = Bt[(size_t)(k0 + kk) * N + colBase + c];
                Bs[kk][c] = v;
            }
        }
        __syncthreads();
#pragma unroll
        for (int kk = 0; kk < 16; kk++) {
            float a[8], b[8];
#pragma unroll
            for (int i = 0; i < 8; i += 4) {
                float4 v = *(const float4*)&As[kk][ty * 8 + i];
                a[i] = v.x; a[i+1] = v.y; a[i+2] = v.z; a[i+3] = v.w;
            }
#pragma unroll
            for (int j = 0; j < 8; j += 4) {
                float4 v = *(const float4*)&Bs[kk][tx * 8 + j];
                b[j] = v.x; b[j+1] = v.y; b[j+2] = v.z; b[j+3] = v.w;
            }
#pragma unroll
            for (int i = 0; i < 8; i++)
#pragma unroll
                for (int j = 0; j < 8; j++) acc[i][j] += a[i] * b[j];
        }
        __syncthreads();
    }
    const float invs = 0.99950037f;   // 1/sqrt(1.001)
#pragma unroll
    for (int i = 0; i < 8; i++) {
        int row = rowBase + ty * 8 + i;
#pragma unroll
        for (int j = 0; j < 8; j++) {
            int col = colBase + tx * 8 + j;
            if (col < N) {
                float v = acc[i][j];
                if (mode >= 1) v += bias[col];
                if (mode == 2) v = gamma[col] * (v * invs) + beta[col];
                C[(size_t)row * N + col] = v;
            }
        }
    }
}

// ---------------- fused GRU step: hg = h@Whhᵀ(+bhh), gates, h update ----------------
// Wt layout: [k(488)][gate*488 + col]. xg includes bih. BM=32, BN=64, BK=16, 256 thr.
__global__ __launch_bounds__(256)
void gru_step(const float* __restrict__ hprev,  // [512][488] or nullptr (h=0)
              const float* __restrict__ xg,     // [512][1464]
              const float* __restrict__ Wt,     // [488][1464]
              const float* __restrict__ bhh,    // [1464]
              float* __restrict__ hout) {       // [512][488]
    __shared__ float As[32][17];
    __shared__ float Ws[3][16][64];
    int tid = threadIdx.x;
    int tx = tid & 15, ty = tid >> 4;
    int rowBase = blockIdx.y * 32;
    int colBase = blockIdx.x * 64;
    float acc[3][2][4];
#pragma unroll
    for (int g = 0; g < 3; g++)
#pragma unroll
        for (int i = 0; i < 2; i++)
#pragma unroll
            for (int j = 0; j < 4; j++) acc[g][i][j] = 0.f;

    for (int k0 = 0; k0 < RECN; k0 += 16) {
        {   // h tile 32x16
            int kk = tid & 15, r0 = tid >> 4;
#pragma unroll
            for (int i = 0; i < 2; i++) {
                int r = r0 + i * 16;
                float v = 0.f;
                if (hprev != nullptr && (k0 + kk) < RECN)
                    v = hprev[(rowBase + r) * RECN + k0 + kk];
                As[r][kk] = v;
            }
        }
        {   // weight tiles 3 x 16 x 64
            int c = tid & 63, kb = tid >> 6;
#pragma unroll
            for (int g = 0; g < 3; g++)
#pragma unroll
                for (int l = 0; l < 4; l++) {
                    int kk = kb + l * 4;
                    float v = 0.f;
                    int col = colBase + c;
                    if (col < RECN && (k0 + kk) < RECN)
                        v = Wt[(size_t)(k0 + kk) * G3N + g * RECN + col];
                    Ws[g][kk][c] = v;
                }
        }
        __syncthreads();
#pragma unroll
        for (int kk = 0; kk < 16; kk++) {
            float a0 = As[ty * 2 + 0][kk];
            float a1 = As[ty * 2 + 1][kk];
#pragma unroll
            for (int g = 0; g < 3; g++) {
                float4 w = *(const float4*)&Ws[g][kk][tx * 4];
                float wv[4] = {w.x, w.y, w.z, w.w};
#pragma unroll
                for (int j = 0; j < 4; j++) {
                    acc[g][0][j] += a0 * wv[j];
                    acc[g][1][j] += a1 * wv[j];
                }
            }
        }
        __syncthreads();
    }
    // epilogue: gates + update
#pragma unroll
    for (int i = 0; i < 2; i++) {
        int b = rowBase + ty * 2 + i;
#pragma unroll
        for (int j = 0; j < 4; j++) {
            int col = colBase + tx * 4 + j;
            if (col < RECN) {
                float hr = acc[0][i][j] + bhh[0 * RECN + col];
                float hz = acc[1][i][j] + bhh[1 * RECN + col];
                float hn = acc[2][i][j] + bhh[2 * RECN + col];
                float xr = xg[(size_t)b * G3N + 0 * RECN + col];
                float xz = xg[(size_t)b * G3N + 1 * RECN + col];
                float xn = xg[(size_t)b * G3N + 2 * RECN + col];
                float r = 1.f / (1.f + expf(-(xr + hr)));
                float z = 1.f / (1.f + expf(-(xz + hz)));
                float n = tanhf(xn + r * hn);
                float hp = (hprev != nullptr) ? hprev[b * RECN + col] : 0.f;
                hout[b * RECN + col] = (1.f - z) * n + z * hp;
            }
        }
    }
}

// ---------------- custom GRU cell: persistent, one block per batch row ----------------
__global__ __launch_bounds__(128)
void cell_all(const float* __restrict__ xg_all,   // [T*512*105], xg = x@Wihᵀ (no bias)
              const float* __restrict__ Whh,      // [105][35]
              const float* __restrict__ bih,      // [105]
              float* __restrict__ out) {          // [512][120][35]
    __shared__ float W[105 * 35];
    __shared__ float bs[105];
    __shared__ float h[NCN], r[NCN], u[NCN];
    __shared__ float e[64];
    int b = blockIdx.x;
    int tid = threadIdx.x;
    for (int i = tid; i < 105 * 35; i += 128) W[i] = Whh[i];
    if (tid < 105) bs[tid] = bih[tid];
    if (tid < NCN) h[tid] = 0.f;
    __syncthreads();

    for (int t = 0; t < TN; t++) {
        const float* xg = xg_all + ((size_t)t * BATCH + b) * (3 * NCN);
        // r and u gates
        if (tid < 70) {
            float s = 0.f;
#pragma unroll
            for (int k = 0; k < NCN; k++) s += h[k] * W[tid * NCN + k];
            float v = 1.f / (1.f + expf(-(xg[tid] + s + bs[tid])));
            if (tid < NCN) r[tid] = v; else u[tid - NCN] = v;
        }
        __syncthreads();
        // n pre-activation
        float npre = -3.0e38f;
        if (tid < NCN) {
            float s = 0.f;
#pragma unroll
            for (int k = 0; k < NCN; k++) s += r[k] * h[k] * W[(70 + tid) * NCN + k];
            npre = xg[70 + tid] + s + bs[70 + tid];
        }
        // softmax over 35 (max-subtracted)
        if (tid < 64) e[tid] = (tid < NCN) ? npre : -3.0e38f;
        __syncthreads();
#pragma unroll
        for (int s2 = 32; s2 > 0; s2 >>= 1) {
            if (tid < s2) e[tid] = fmaxf(e[tid], e[tid + s2]);
            __syncthreads();
        }
        float mx = e[0];
        __syncthreads();
        float ex = 0.f;
        if (tid < NCN) ex = expf(npre - mx);
        if (tid < 64) e[tid] = (tid < NCN) ? ex : 0.f;
        __syncthreads();
#pragma unroll
        for (int s2 = 32; s2 > 0; s2 >>= 1) {
            if (tid < s2) e[tid] += e[tid + s2];
            __syncthreads();
        }
        float sum = e[0];
        float h2 = 0.f;
        if (tid < NCN) {
            float n = ex / sum;
            h2 = (1.f - u[tid]) * n + u[tid] * h[tid];
            out[(size_t)b * (TN * NCN) + t * NCN + tid] = h2;
        }
        __syncthreads();
        if (tid < NCN) h[tid] = h2;
        __syncthreads();
    }
}

// ---------------- launch ----------------
static inline int ceil_div(int a, int b) { return (a + b - 1) / b; }

extern "C" void kernel_launch(void* const* d_in, const int* in_sizes, int n_in,
                              void* d_out, int out_size) {
    const float* z_in     = (const float*)d_in[0];
    const float* W0       = (const float*)d_in[1];
    const float* b0       = (const float*)d_in[2];
    const float* g0       = (const float*)d_in[3];
    const float* beta0    = (const float*)d_in[4];
    const float* W1       = (const float*)d_in[5];
    const float* b1       = (const float*)d_in[6];
    const float* g1       = (const float*)d_in[7];
    const float* beta1    = (const float*)d_in[8];
    const float* gru0_Wih = (const float*)d_in[9];
    const float* gru0_Whh = (const float*)d_in[10];
    const float* gru0_bih = (const float*)d_in[11];
    const float* gru0_bhh = (const float*)d_in[12];
    const float* gru1_Wih = (const float*)d_in[13];
    const float* gru1_Whh = (const float*)d_in[14];
    const float* gru1_bih = (const float*)d_in[15];
    const float* gru1_bhh = (const float*)d_in[16];
    const float* cell_Wih = (const float*)d_in[17];
    const float* cell_Whh = (const float*)d_in[18];
    const float* cell_bih = (const float*)d_in[19];
    float* out = (float*)d_out;

    float *z1, *z2, *xg0, *X0, *XG1, *X1, *XGc;
    float *WtD0, *WtD1, *Wt0x, *Wt0h, *Wt1x, *Wt1h, *Wtc;
    cudaGetSymbolAddress((void**)&z1,  g_z1);
    cudaGetSymbolAddress((void**)&z2,  g_z2);
    cudaGetSymbolAddress((void**)&xg0, g_xg0);
    cudaGetSymbolAddress((void**)&X0,  g_X0);
    cudaGetSymbolAddress((void**)&XG1, g_XG1);
    cudaGetSymbolAddress((void**)&X1,  g_X1);
    cudaGetSymbolAddress((void**)&XGc, g_XGc);
    cudaGetSymbolAddress((void**)&WtD0, g_WtD0);
    cudaGetSymbolAddress((void**)&WtD1, g_WtD1);
    cudaGetSymbolAddress((void**)&Wt0x, g_Wt0x);
    cudaGetSymbolAddress((void**)&Wt0h, g_Wt0h);
    cudaGetSymbolAddress((void**)&Wt1x, g_Wt1x);
    cudaGetSymbolAddress((void**)&Wt1h, g_Wt1h);
    cudaGetSymbolAddress((void**)&Wtc,  g_Wtc);

    dim3 tb(32, 8);
    // transposes: in[R][C] -> out[C][R]
    transpose_k<<<dim3(ceil_div(HIDN,32), ceil_div(HIDN,32)), tb>>>(W0, WtD0, HIDN, HIDN);
    transpose_k<<<dim3(ceil_div(HIDN,32), ceil_div(HIDN,32)), tb>>>(W1, WtD1, HIDN, HIDN);
    transpose_k<<<dim3(ceil_div(HIDN,32), ceil_div(G3N,32)), tb>>>(gru0_Wih, Wt0x, G3N, HIDN);
    transpose_k<<<dim3(ceil_div(RECN,32), ceil_div(G3N,32)), tb>>>(gru0_Whh, Wt0h, G3N, RECN);
    transpose_k<<<dim3(ceil_div(RECN,32), ceil_div(G3N,32)), tb>>>(gru1_Wih, Wt1x, G3N, RECN);
    transpose_k<<<dim3(ceil_div(RECN,32), ceil_div(G3N,32)), tb>>>(gru1_Whh, Wt1h, G3N, RECN);
    transpose_k<<<dim3(ceil_div(RECN,32), ceil_div(3*NCN,32)), tb>>>(cell_Wih, Wtc, 3*NCN, RECN);

    // dense + BN x2
    gemm128<<<dim3(ceil_div(HIDN,128), BATCH/128), 256>>>(
        z_in, WtD0, b0, g0, beta0, z1, BATCH, HIDN, HIDN, 2);
    gemm128<<<dim3(ceil_div(HIDN,128), BATCH/128), 256>>>(
        z1, WtD1, b1, g1, beta1, z2, BATCH, HIDN, HIDN, 2);

    // GRU0 input gates (time-invariant): xg0 = z2 @ Wih0ᵀ + bih0
    gemm128<<<dim3(ceil_div(G3N,128), BATCH/128), 256>>>(
        z2, Wt0x, gru0_bih, nullptr, nullptr, xg0, BATCH, G3N, HIDN, 1);

    // GRU0 recurrence
    dim3 gsGrid(ceil_div(RECN, 64), BATCH / 32);
    for (int t = 0; t < TN; t++) {
        const float* hp = (t == 0) ? nullptr : (X0 + (size_t)(t - 1) * BH);
        gru_step<<<gsGrid, 256>>>(hp, xg0, Wt0h, gru0_bhh, X0 + (size_t)t * BH);
    }

    // GRU1 input gates for all T at once: XG1 = X0 @ Wih1ᵀ + bih1
    gemm128<<<dim3(ceil_div(G3N,128), (TN * BATCH) / 128), 256>>>(
        X0, Wt1x, gru1_bih, nullptr, nullptr, XG1, TN * BATCH, G3N, RECN, 1);

    // GRU1 recurrence
    for (int t = 0; t < TN; t++) {
        const float* hp = (t == 0) ? nullptr : (X1 + (size_t)(t - 1) * BH);
        gru_step<<<gsGrid, 256>>>(hp, XG1 + (size_t)t * BG, Wt1h, gru1_bhh,
                                  X1 + (size_t)t * BH);
    }

    // cell input gates for all T: XGc = X1 @ cell_Wihᵀ
    gemm128<<<dim3(ceil_div(3*NCN,128), (TN * BATCH) / 128), 256>>>(
        X1, Wtc, nullptr, nullptr, nullptr, XGc, TN * BATCH, 3 * NCN, RECN, 0);

    // custom cell recurrence: fully parallel over batch, one persistent kernel
    cell_all<<<BATCH, 128>>>(XGc, cell_Whh, cell_bih, out);
}

// round 2
// speedup vs baseline: 1.0604x; 1.0604x over previous
#include <cuda_runtime.h>
#include <math.h>
#include <stdint.h>

#define BATCH 512
#define HIDN  196
#define RECN  488
#define G3N   1464      // 3*RECN
#define NCN   35
#define TN    120
#define BH    (BATCH*RECN)
#define BG    (BATCH*G3N)

typedef unsigned long long ull;

// ---------------- f32x2 packed-FMA helpers (Blackwell FFMA2) ----------------
__device__ __forceinline__ ull dup2(float x) {
    ull r; asm("mov.b64 %0, {%1, %1};" : "=l"(r) : "f"(x)); return r;
}
__device__ __forceinline__ void fma2(ull& d, ull a, ull b) {
    asm("fma.rn.f32x2 %0, %1, %2, %0;" : "+l"(d) : "l"(a), "l"(b));
}
__device__ __forceinline__ float2 unpk(ull v) {
    float2 r; asm("mov.b64 {%0, %1}, %2;" : "=f"(r.x), "=f"(r.y) : "l"(v)); return r;
}
__device__ __forceinline__ float sigmf(float x) { return 1.f / (1.f + __expf(-x)); }
__device__ __forceinline__ float tanhfast(float x) { return 1.f - 2.f / (__expf(2.f * x) + 1.f); }

// ---------------- scratch (static device allocations) ----------------
__device__ float g_z1 [BATCH*HIDN];
__device__ float g_z2 [BATCH*HIDN];
__device__ float g_xg0[BATCH*G3N];
__device__ float g_X0 [(size_t)TN*BATCH*RECN];
__device__ float g_XG1[(size_t)TN*BATCH*G3N];
__device__ float g_X1 [(size_t)TN*BATCH*RECN];
__device__ float g_XGc[(size_t)TN*BATCH*3*NCN];
__device__ float g_WtD0[HIDN*HIDN];
__device__ float g_WtD1[HIDN*HIDN];
__device__ float g_Wt0x[HIDN*G3N];
__device__ float g_Wt0h[RECN*G3N];
__device__ float g_Wt1x[RECN*G3N];
__device__ float g_Wt1h[RECN*G3N];
__device__ float g_Wtc [RECN*3*NCN];

// ---------------- transpose: in[R][C] -> out[C][R] ----------------
__global__ void transpose_k(const float* __restrict__ in, float* __restrict__ out,
                            int R, int C) {
    __shared__ float tile[32][33];
    int c0 = blockIdx.x * 32, r0 = blockIdx.y * 32;
    int tx = threadIdx.x, ty = threadIdx.y;
    for (int i = ty; i < 32; i += 8) {
        int r = r0 + i, c = c0 + tx;
        tile[i][tx] = (r < R && c < C) ? in[(size_t)r * C + c] : 0.f;
    }
    __syncthreads();
    for (int i = ty; i < 32; i += 8) {
        int r = r0 + tx, c = c0 + i;
        if (c < C && r < R) out[(size_t)c * R + r] = tile[tx][i];
    }
}

// ---------------- 128x128 tiled SGEMM with FFMA2: C = A[MxK] @ Bt[KxN] ----------------
// mode 0: C=acc   mode 1: C=acc+bias   mode 2: fused BN
__global__ __launch_bounds__(256)
void gemm128(const float* __restrict__ A, const float* __restrict__ Bt,
             const float* __restrict__ bias, const float* __restrict__ gamma,
             const float* __restrict__ beta, float* __restrict__ C,
             int M, int N, int K, int mode) {
    __shared__ float As[16][132];     // 132*4=528B rows -> 16B aligned
    __shared__ float Bs[16][128];
    int tid = threadIdx.x;
    int tx = tid & 15, ty = tid >> 4;
    int rowBase = blockIdx.y * 128, colBase = blockIdx.x * 128;
    ull acc[8][4];
#pragma unroll
    for (int i = 0; i < 8; i++)
#pragma unroll
        for (int j = 0; j < 4; j++) acc[i][j] = 0ULL;

    for (int k0 = 0; k0 < K; k0 += 16) {
        {   // A tile: 128 x 16
            int kk = tid & 15, m0 = tid >> 4;
#pragma unroll
            for (int l = 0; l < 8; l++) {
                int m = m0 + l * 16;
                float v = 0.f;
                if (k0 + kk < K) v = A[(size_t)(rowBase + m) * K + k0 + kk];
                As[kk][m] = v;
            }
        }
        {   // B tile: 16 x 128
            int c = tid & 127, kb = tid >> 7;
#pragma unroll
            for (int l = 0; l < 8; l++) {
                int kk = kb + l * 2;
                float v = 0.f;
                if ((k0 + kk) < K && (colBase + c) < N)
                    v = Bt[(size_t)(k0 + kk) * N + colBase + c];
                Bs[kk][c] = v;
            }
        }
        __syncthreads();
#pragma unroll
        for (int kk = 0; kk < 16; kk++) {
            float4 av0 = *(const float4*)&As[kk][ty * 8];
            float4 av1 = *(const float4*)&As[kk][ty * 8 + 4];
            ull a2[8];
            a2[0] = dup2(av0.x); a2[1] = dup2(av0.y); a2[2] = dup2(av0.z); a2[3] = dup2(av0.w);
            a2[4] = dup2(av1.x); a2[5] = dup2(av1.y); a2[6] = dup2(av1.z); a2[7] = dup2(av1.w);
            const ulonglong2* bp = (const ulonglong2*)&Bs[kk][tx * 8];
            ulonglong2 bv0 = bp[0], bv1 = bp[1];
            ull b2[4] = {bv0.x, bv0.y, bv1.x, bv1.y};
#pragma unroll
            for (int i = 0; i < 8; i++)
#pragma unroll
                for (int j = 0; j < 4; j++) fma2(acc[i][j], a2[i], b2[j]);
        }
        __syncthreads();
    }
    const float invs = 0.99950037f;   // 1/sqrt(1.001)
#pragma unroll
    for (int i = 0; i < 8; i++) {
        int row = rowBase + ty * 8 + i;
#pragma unroll
        for (int j = 0; j < 4; j++) {
            float2 p = unpk(acc[i][j]);
#pragma unroll
            for (int s = 0; s < 2; s++) {
                int col = colBase + tx * 8 + j * 2 + s;
                if (col < N) {
                    float v = (s == 0) ? p.x : p.y;
                    if (mode >= 1) v += bias[col];
                    if (mode == 2) v = gamma[col] * (v * invs) + beta[col];
                    C[(size_t)row * N + col] = v;
                }
            }
        }
    }
}

// ---------------- fused GRU step with FFMA2 ----------------
// BM=64 rows, BN=32 cols (x3 gates), BK=16, 256 threads, grid (16, 8) = 128 blocks.
// Wt layout: [k(488)][gate*488 + col]. xg includes bih.
__global__ __launch_bounds__(256)
void gru_step(const float* __restrict__ hprev,  // [512][488] or nullptr (h=0)
              const float* __restrict__ xg,     // [512][1464]
              const float* __restrict__ Wt,     // [488][1464]
              const float* __restrict__ bhh,    // [1464]
              float* __restrict__ hout) {       // [512][488]
    __shared__ float As[16][68];      // [kk][row], 68*4=272B rows -> 16B aligned
    __shared__ float Ws[3][16][32];   // [gate][kk][col]
    int tid = threadIdx.x;
    int tx = tid & 15, ty = tid >> 4;           // tx: col pair, ty: 4-row group
    int rowBase = blockIdx.y * 64;
    int colBase = blockIdx.x * 32;
    ull acc[3][4];
#pragma unroll
    for (int g = 0; g < 3; g++)
#pragma unroll
        for (int i = 0; i < 4; i++) acc[g][i] = 0ULL;

    for (int k0 = 0; k0 < RECN; k0 += 16) {
        {   // h tile: 64 rows x 16 k  -> As[kk][row]
            int kk = tid & 15, r0 = tid >> 4;
#pragma unroll
            for (int i = 0; i < 4; i++) {
                int r = r0 + i * 16;
                float v = 0.f;
                if (hprev != nullptr && (k0 + kk) < RECN)
                    v = hprev[(size_t)(rowBase + r) * RECN + k0 + kk];
                As[kk][r] = v;
            }
        }
        {   // weight tiles: 3 gates x 16 k x 32 cols
            int c = tid & 31, q = tid >> 5;     // q in 0..7
#pragma unroll
            for (int l = 0; l < 6; l++) {
                int idx = q + l * 8;            // 0..47
                int g = idx >> 4, kk = idx & 15;
                float v = 0.f;
                int col = colBase + c;
                if (col < RECN && (k0 + kk) < RECN)
                    v = Wt[(size_t)(k0 + kk) * G3N + g * RECN + col];
                Ws[g][kk][c] = v;
            }
        }
        __syncthreads();
#pragma unroll
        for (int kk = 0; kk < 16; kk++) {
            float4 av = *(const float4*)&As[kk][ty * 4];
            ull a2[4] = {dup2(av.x), dup2(av.y), dup2(av.z), dup2(av.w)};
            ull w0 = *(const ull*)&Ws[0][kk][tx * 2];
            ull w1 = *(const ull*)&Ws[1][kk][tx * 2];
            ull w2 = *(const ull*)&Ws[2][kk][tx * 2];
#pragma unroll
            for (int i = 0; i < 4; i++) {
                fma2(acc[0][i], a2[i], w0);
                fma2(acc[1][i], a2[i], w1);
                fma2(acc[2][i], a2[i], w2);
            }
        }
        __syncthreads();
    }
    // epilogue: gates + h update
#pragma unroll
    for (int i = 0; i < 4; i++) {
        int b = rowBase + ty * 4 + i;
        float2 hrv = unpk(acc[0][i]);
        float2 hzv = unpk(acc[1][i]);
        float2 hnv = unpk(acc[2][i]);
#pragma unroll
        for (int j = 0; j < 2; j++) {
            int col = colBase + tx * 2 + j;
            if (col < RECN) {
                float hr = (j ? hrv.y : hrv.x) + bhh[0 * RECN + col];
                float hz = (j ? hzv.y : hzv.x) + bhh[1 * RECN + col];
                float hn = (j ? hnv.y : hnv.x) + bhh[2 * RECN + col];
                const float* xgb = xg + (size_t)b * G3N;
                float r = sigmf(xgb[0 * RECN + col] + hr);
                float z = sigmf(xgb[1 * RECN + col] + hz);
                float n = tanhfast(xgb[2 * RECN + col] + r * hn);
                float hp = (hprev != nullptr) ? hprev[(size_t)b * RECN + col] : 0.f;
                hout[(size_t)b * RECN + col] = (1.f - z) * n + z * hp;
            }
        }
    }
}

// ---------------- custom GRU cell: persistent, one block per batch row ----------------
__global__ __launch_bounds__(128)
void cell_all(const float* __restrict__ xg_all,   // [T*512*105]
              const float* __restrict__ Whh,      // [105][35]
              const float* __restrict__ bih,      // [105]
              float* __restrict__ out) {          // [512][120][35]
    __shared__ float W[105 * 35];
    __shared__ float bs[105];
    __shared__ float h[NCN], r[NCN], u[NCN];
    __shared__ float e[64];
    int b = blockIdx.x;
    int tid = threadIdx.x;
    for (int i = tid; i < 105 * 35; i += 128) W[i] = Whh[i];
    if (tid < 105) bs[tid] = bih[tid];
    if (tid < NCN) h[tid] = 0.f;
    __syncthreads();

    for (int t = 0; t < TN; t++) {
        const float* xgp = xg_all + ((size_t)t * BATCH + b) * (3 * NCN);
        if (tid < 70) {
            float s = 0.f;
#pragma unroll
            for (int k = 0; k < NCN; k++) s += h[k] * W[tid * NCN + k];
            float v = sigmf(xgp[tid] + s + bs[tid]);
            if (tid < NCN) r[tid] = v; else u[tid - NCN] = v;
        }
        __syncthreads();
        float npre = -3.0e38f;
        if (tid < NCN) {
            float s = 0.f;
#pragma unroll
            for (int k = 0; k < NCN; k++) s += r[k] * h[k] * W[(70 + tid) * NCN + k];
            npre = xgp[70 + tid] + s + bs[70 + tid];
        }
        if (tid < 64) e[tid] = (tid < NCN) ? npre : -3.0e38f;
        __syncthreads();
        if (tid < 32) {
            float v = fmaxf(e[tid], e[tid + 32]);
#pragma unroll
            for (int o = 16; o > 0; o >>= 1) v = fmaxf(v, __shfl_xor_sync(0xffffffffu, v, o));
            if (tid == 0) e[0] = v;
        }
        __syncthreads();
        float mx = e[0];
        __syncthreads();
        float ex = 0.f;
        if (tid < NCN) ex = __expf(npre - mx);
        if (tid < 64) e[tid] = (tid < NCN) ? ex : 0.f;
        __syncthreads();
        if (tid < 32) {
            float v = e[tid] + e[tid + 32];
#pragma unroll
            for (int o = 16; o > 0; o >>= 1) v += __shfl_xor_sync(0xffffffffu, v, o);
            if (tid == 0) e[0] = v;
        }
        __syncthreads();
        float sum = e[0];
        float h2 = 0.f;
        if (tid < NCN) {
            float n = ex / sum;
            h2 = (1.f - u[tid]) * n + u[tid] * h[tid];
            out[(size_t)b * (TN * NCN) + t * NCN + tid] = h2;
        }
        __syncthreads();
        if (tid < NCN) h[tid] = h2;
        __syncthreads();
    }
}

// ---------------- launch ----------------
static inline int ceil_div(int a, int b) { return (a + b - 1) / b; }

extern "C" void kernel_launch(void* const* d_in, const int* in_sizes, int n_in,
                              void* d_out, int out_size) {
    const float* z_in     = (const float*)d_in[0];
    const float* W0       = (const float*)d_in[1];
    const float* b0       = (const float*)d_in[2];
    const float* g0       = (const float*)d_in[3];
    const float* beta0    = (const float*)d_in[4];
    const float* W1       = (const float*)d_in[5];
    const float* b1       = (const float*)d_in[6];
    const float* g1       = (const float*)d_in[7];
    const float* beta1    = (const float*)d_in[8];
    const float* gru0_Wih = (const float*)d_in[9];
    const float* gru0_Whh = (const float*)d_in[10];
    const float* gru0_bih = (const float*)d_in[11];
    const float* gru0_bhh = (const float*)d_in[12];
    const float* gru1_Wih = (const float*)d_in[13];
    const float* gru1_Whh = (const float*)d_in[14];
    const float* gru1_bih = (const float*)d_in[15];
    const float* gru1_bhh = (const float*)d_in[16];
    const float* cell_Wih = (const float*)d_in[17];
    const float* cell_Whh = (const float*)d_in[18];
    const float* cell_bih = (const float*)d_in[19];
    float* out = (float*)d_out;

    float *z1, *z2, *xg0, *X0, *XG1, *X1, *XGc;
    float *WtD0, *WtD1, *Wt0x, *Wt0h, *Wt1x, *Wt1h, *Wtc;
    cudaGetSymbolAddress((void**)&z1,  g_z1);
    cudaGetSymbolAddress((void**)&z2,  g_z2);
    cudaGetSymbolAddress((void**)&xg0, g_xg0);
    cudaGetSymbolAddress((void**)&X0,  g_X0);
    cudaGetSymbolAddress((void**)&XG1, g_XG1);
    cudaGetSymbolAddress((void**)&X1,  g_X1);
    cudaGetSymbolAddress((void**)&XGc, g_XGc);
    cudaGetSymbolAddress((void**)&WtD0, g_WtD0);
    cudaGetSymbolAddress((void**)&WtD1, g_WtD1);
    cudaGetSymbolAddress((void**)&Wt0x, g_Wt0x);
    cudaGetSymbolAddress((void**)&Wt0h, g_Wt0h);
    cudaGetSymbolAddress((void**)&Wt1x, g_Wt1x);
    cudaGetSymbolAddress((void**)&Wt1h, g_Wt1h);
    cudaGetSymbolAddress((void**)&Wtc,  g_Wtc);

    dim3 tb(32, 8);
    transpose_k<<<dim3(ceil_div(HIDN,32), ceil_div(HIDN,32)), tb>>>(W0, WtD0, HIDN, HIDN);
    transpose_k<<<dim3(ceil_div(HIDN,32), ceil_div(HIDN,32)), tb>>>(W1, WtD1, HIDN, HIDN);
    transpose_k<<<dim3(ceil_div(HIDN,32), ceil_div(G3N,32)), tb>>>(gru0_Wih, Wt0x, G3N, HIDN);
    transpose_k<<<dim3(ceil_div(RECN,32), ceil_div(G3N,32)), tb>>>(gru0_Whh, Wt0h, G3N, RECN);
    transpose_k<<<dim3(ceil_div(RECN,32), ceil_div(G3N,32)), tb>>>(gru1_Wih, Wt1x, G3N, RECN);
    transpose_k<<<dim3(ceil_div(RECN,32), ceil_div(G3N,32)), tb>>>(gru1_Whh, Wt1h, G3N, RECN);
    transpose_k<<<dim3(ceil_div(RECN,32), ceil_div(3*NCN,32)), tb>>>(cell_Wih, Wtc, 3*NCN, RECN);

    // dense + BN x2
    gemm128<<<dim3(ceil_div(HIDN,128), BATCH/128), 256>>>(
        z_in, WtD0, b0, g0, beta0, z1, BATCH, HIDN, HIDN, 2);
    gemm128<<<dim3(ceil_div(HIDN,128), BATCH/128), 256>>>(
        z1, WtD1, b1, g1, beta1, z2, BATCH, HIDN, HIDN, 2);

    // GRU0 input gates (time-invariant)
    gemm128<<<dim3(ceil_div(G3N,128), BATCH/128), 256>>>(
        z2, Wt0x, gru0_bih, nullptr, nullptr, xg0, BATCH, G3N, HIDN, 1);

    // GRU0 recurrence
    dim3 gsGrid(ceil_div(RECN, 32), BATCH / 64);   // (16, 8) = 128 blocks
    for (int t = 0; t < TN; t++) {
        const float* hp = (t == 0) ? nullptr : (X0 + (size_t)(t - 1) * BH);
        gru_step<<<gsGrid, 256>>>(hp, xg0, Wt0h, gru0_bhh, X0 + (size_t)t * BH);
    }

    // GRU1 input gates for all T at once
    gemm128<<<dim3(ceil_div(G3N,128), (TN * BATCH) / 128), 256>>>(
        X0, Wt1x, gru1_bih, nullptr, nullptr, XG1, TN * BATCH, G3N, RECN, 1);

    // GRU1 recurrence
    for (int t = 0; t < TN; t++) {
        const float* hp = (t == 0) ? nullptr : (X1 + (size_t)(t - 1) * BH);
        gru_step<<<gsGrid, 256>>>(hp, XG1 + (size_t)t * BG, Wt1h, gru1_bhh,
                                  X1 + (size_t)t * BH);
    }

    // cell input gates for all T
    gemm128<<<dim3(ceil_div(3*NCN,128), (TN * BATCH) / 128), 256>>>(
        X1, Wtc, nullptr, nullptr, nullptr, XGc, TN * BATCH, 3 * NCN, RECN, 0);

    // custom cell recurrence
    cell_all<<<BATCH, 128>>>(XGc, cell_Whh, cell_bih, out);
}

// round 4
// speedup vs baseline: 1.1824x; 1.1151x over previous
#include <cuda_runtime.h>
#include <stdint.h>

#define BATCH 512
#define HIDN  196
#define RECN  488
#define G3N   1464
#define G3P   1536     // gate-padded: 3 x 512
#define KPH   208      // HIDN padded to mult of 16
#define KPR   496      // RECN padded to mult of 16
#define NCN   35
#define NC3   105
#define NCP   128
#define TN    120
#define BHP   (BATCH*KPR)
#define BGP   (BATCH*G3P)

typedef unsigned long long ull;

// ---------------- f32x2 helpers ----------------
__device__ __forceinline__ ull dup2(float x) {
    ull r; asm("mov.b64 %0, {%1, %1};" : "=l"(r) : "f"(x)); return r;
}
__device__ __forceinline__ void fma2(ull& d, ull a, ull b) {
    asm("fma.rn.f32x2 %0, %1, %2, %0;" : "+l"(d) : "l"(a), "l"(b));
}
__device__ __forceinline__ float2 unpk(ull v) {
    float2 r; asm("mov.b64 {%0, %1}, %2;" : "=f"(r.x), "=f"(r.y) : "l"(v)); return r;
}
__device__ __forceinline__ float sigmf(float x) { return 1.f / (1.f + __expf(-x)); }
__device__ __forceinline__ float tanhfast(float x) { return 1.f - 2.f / (__expf(2.f * x) + 1.f); }

__device__ __forceinline__ uint32_t smaddr(const void* p) {
    return (uint32_t)__cvta_generic_to_shared(p);
}
__device__ __forceinline__ void cp16(void* dst, const void* src) {
    asm volatile("cp.async.ca.shared.global [%0], [%1], 16;" :: "r"(smaddr(dst)), "l"(src));
}
__device__ __forceinline__ void cp8(void* dst, const void* src) {
    asm volatile("cp.async.ca.shared.global [%0], [%1], 8;" :: "r"(smaddr(dst)), "l"(src));
}
__device__ __forceinline__ void cp_commit() { asm volatile("cp.async.commit_group;"); }
__device__ __forceinline__ void cp_wait0()  { asm volatile("cp.async.wait_group 0;" ::: "memory"); }

// ---------------- scratch ----------------
__device__ float g_z1 [BATCH*HIDN];
__device__ float g_z2 [BATCH*KPH];                  // padded cols zero
__device__ float g_xg0[(size_t)BATCH*G3P];
__device__ float g_X0 [(size_t)TN*BATCH*KPR];       // pad cols stay zero
__device__ float g_XG1[(size_t)TN*BATCH*G3P];
__device__ float g_X1 [(size_t)TN*BATCH*KPR];
__device__ float g_XGc[(size_t)TN*BATCH*NCP];
__device__ float g_WtD0[HIDN*HIDN];
__device__ float g_WtD1[HIDN*HIDN];
__device__ float g_Wt0x[(size_t)KPH*G3P];
__device__ float g_Wt0h[(size_t)KPR*G3P];
__device__ float g_Wt1x[(size_t)KPR*G3P];
__device__ float g_Wt1h[(size_t)KPR*G3P];
__device__ float g_Wtc [(size_t)KPR*NCP];

// ---------------- fused transpose/pack (7 jobs) ----------------
// dst[k][c]; gate jobs remap c -> (g, n) with gate stride 512, zero padding.
// tile[a][b] holds value for (c = c0+a, k = r0+b).
__global__ void trans_all(
    const float* __restrict__ W0,  const float* __restrict__ W1,
    const float* __restrict__ Wih0,const float* __restrict__ Whh0,
    const float* __restrict__ Wih1,const float* __restrict__ Whh1,
    const float* __restrict__ Wc,
    float* __restrict__ WtD0, float* __restrict__ WtD1,
    float* __restrict__ Wt0x, float* __restrict__ Wt0h,
    float* __restrict__ Wt1x, float* __restrict__ Wt1h,
    float* __restrict__ Wtc)
{
    int j = blockIdx.z;
    const float* src; float* dst;
    int DR, DC, SK, NV, gate;
    switch (j) {
      case 0: src=W0;   dst=WtD0; DR=HIDN; DC=HIDN; SK=HIDN; NV=HIDN; gate=0; break;
      case 1: src=W1;   dst=WtD1; DR=HIDN; DC=HIDN; SK=HIDN; NV=HIDN; gate=0; break;
      case 2: src=Wih0; dst=Wt0x; DR=KPH;  DC=G3P;  SK=HIDN; NV=RECN; gate=1; break;
      case 3: src=Whh0; dst=Wt0h; DR=KPR;  DC=G3P;  SK=RECN; NV=RECN; gate=1; break;
      case 4: src=Wih1; dst=Wt1x; DR=KPR;  DC=G3P;  SK=RECN; NV=RECN; gate=1; break;
      case 5: src=Whh1; dst=Wt1h; DR=KPR;  DC=G3P;  SK=RECN; NV=RECN; gate=1; break;
      default:src=Wc;   dst=Wtc;  DR=KPR;  DC=NCP;  SK=RECN; NV=NC3;  gate=0; break;
    }
    int r0 = blockIdx.y * 32, c0 = blockIdx.x * 32;
    if (r0 >= DR || c0 >= DC) return;
    __shared__ float tile[32][33];
    int tx = threadIdx.x, ty = threadIdx.y;
    // load: coalesced over k (src rows contiguous in k)
    for (int i = ty; i < 32; i += 8) {
        int c = c0 + i, k = r0 + tx;
        float v = 0.f;
        if (c < DC && k < SK) {
            int n  = gate ? (c & 511) : c;
            int sr = gate ? ((c >> 9) * RECN + n) : c;
            if (n < NV) v = src[(size_t)sr * SK + k];
        }
        tile[i][tx] = v;
    }
    __syncthreads();
    // store: dst[k = r0+i][c = c0+tx] = tile[tx][i]  (coalesced over c)
    for (int i = ty; i < 32; i += 8) {
        int r = r0 + i, c = c0 + tx;
        if (r < DR && c < DC) dst[(size_t)r * DC + c] = tile[tx][i];
    }
}

// ---------------- small GEMM for dense+BN (guarded, single-buffered) ----------------
__global__ __launch_bounds__(256)
void gemm_naive(const float* __restrict__ A, const float* __restrict__ Bt,
                const float* __restrict__ bias, const float* __restrict__ gamma,
                const float* __restrict__ beta, float* __restrict__ C,
                int M, int N, int K, int ldc) {
    __shared__ float As[16][132];
    __shared__ float Bs[16][128];
    int tid = threadIdx.x;
    int tx = tid & 15, ty = tid >> 4;
    int rowBase = blockIdx.y * 128, colBase = blockIdx.x * 128;
    ull acc[8][4];
#pragma unroll
    for (int i = 0; i < 8; i++)
#pragma unroll
        for (int j = 0; j < 4; j++) acc[i][j] = 0ULL;

    for (int k0 = 0; k0 < K; k0 += 16) {
        {
            int kk = tid & 15, m0 = tid >> 4;
#pragma unroll
            for (int l = 0; l < 8; l++) {
                int m = m0 + l * 16;
                float v = 0.f;
                if (k0 + kk < K) v = A[(size_t)(rowBase + m) * K + k0 + kk];
                As[kk][m] = v;
            }
        }
        {
            int c = tid & 127, kb = tid >> 7;
#pragma unroll
            for (int l = 0; l < 8; l++) {
                int kk = kb + l * 2;
                float v = 0.f;
                if ((k0 + kk) < K && (colBase + c) < N)
                    v = Bt[(size_t)(k0 + kk) * N + colBase + c];
                Bs[kk][c] = v;
            }
        }
        __syncthreads();
#pragma unroll
        for (int kk = 0; kk < 16; kk++) {
            float4 av0 = *(const float4*)&As[kk][ty * 8];
            float4 av1 = *(const float4*)&As[kk][ty * 8 + 4];
            ull a2[8];
            a2[0]=dup2(av0.x); a2[1]=dup2(av0.y); a2[2]=dup2(av0.z); a2[3]=dup2(av0.w);
            a2[4]=dup2(av1.x); a2[5]=dup2(av1.y); a2[6]=dup2(av1.z); a2[7]=dup2(av1.w);
            const ulonglong2* bp = (const ulonglong2*)&Bs[kk][tx * 8];
            ulonglong2 bv0 = bp[0], bv1 = bp[1];
            ull b2[4] = {bv0.x, bv0.y, bv1.x, bv1.y};
#pragma unroll
            for (int i = 0; i < 8; i++)
#pragma unroll
                for (int j = 0; j < 4; j++) fma2(acc[i][j], a2[i], b2[j]);
        }
        __syncthreads();
    }
    const float invs = 0.99950037f;   // 1/sqrt(1.001)
#pragma unroll
    for (int i = 0; i < 8; i++) {
        int row = rowBase + ty * 8 + i;
        if (row >= M) continue;
#pragma unroll
        for (int j = 0; j < 4; j++) {
            float2 p = unpk(acc[i][j]);
#pragma unroll
            for (int s = 0; s < 2; s++) {
                int col = colBase + tx * 8 + j * 2 + s;
                if (col < N) {
                    float v = (s == 0) ? p.x : p.y;
                    v += bias[col];
                    v = gamma[col] * (v * invs) + beta[col];
                    C[(size_t)row * ldc + col] = v;
                }
            }
        }
    }
}

// ---------------- pipelined 128x128 GEMM (padded, unguarded hot loop) ----------------
__global__ __launch_bounds__(256)
void gemmP(const float* __restrict__ A, int lda, int KP,
           const float* __restrict__ B, int NP,
           const float* __restrict__ bias, int gate, int Nvalid,
           float* __restrict__ C)
{
    __shared__ ull   Ad[2][16][128];   // pre-duplicated f32x2 pairs  (32KB)
    __shared__ float Bs[2][16][128];   // (16KB)
    int tid = threadIdx.x;
    int tx = tid & 15, ty = tid >> 4;
    size_t rowBase = (size_t)blockIdx.y * 128;
    int colBase = blockIdx.x * 128;
    int NT = KP >> 4;

    ull acc[8][4];
#pragma unroll
    for (int i = 0; i < 8; i++)
#pragma unroll
        for (int j = 0; j < 4; j++) acc[i][j] = 0ULL;

    int arow[2], akq[2], bkk[2], bc4[2];
#pragma unroll
    for (int l = 0; l < 2; l++) {
        int idx = tid + l * 256;
        arow[l] = idx >> 2;  akq[l] = idx & 3;
        bkk[l]  = idx >> 5;  bc4[l] = idx & 31;
    }

    // prologue: tile 0
    float4 a0[2];
#pragma unroll
    for (int l = 0; l < 2; l++)
        a0[l] = *(const float4*)(A + (rowBase + arow[l]) * lda + akq[l] * 4);
#pragma unroll
    for (int l = 0; l < 2; l++)
        cp16(&Bs[0][bkk[l]][bc4[l] * 4], B + (size_t)bkk[l] * NP + colBase + bc4[l] * 4);
    cp_commit();
#pragma unroll
    for (int l = 0; l < 2; l++) {
        float f[4] = {a0[l].x, a0[l].y, a0[l].z, a0[l].w};
#pragma unroll
        for (int q = 0; q < 4; q++) Ad[0][akq[l] * 4 + q][arow[l]] = dup2(f[q]);
    }

    for (int kt = 0; kt < NT; kt++) {
        int cb = kt & 1, nb = (kt + 1) & 1;
        float4 an[2];
        bool more = (kt + 1 < NT);
        if (more) {
#pragma unroll
            for (int l = 0; l < 2; l++)
                an[l] = *(const float4*)(A + (rowBase + arow[l]) * lda + (kt + 1) * 16 + akq[l] * 4);
        }
        cp_wait0();
        __syncthreads();
        if (more) {
#pragma unroll
            for (int l = 0; l < 2; l++)
                cp16(&Bs[nb][bkk[l]][bc4[l] * 4],
                     B + (size_t)((kt + 1) * 16 + bkk[l]) * NP + colBase + bc4[l] * 4);
            cp_commit();
        }
#pragma unroll
        for (int kk = 0; kk < 16; kk++) {
            const ulonglong2* ap = (const ulonglong2*)&Ad[cb][kk][ty * 8];
            ulonglong2 v0 = ap[0], v1 = ap[1], v2 = ap[2], v3 = ap[3];
            ull a2[8] = {v0.x, v0.y, v1.x, v1.y, v2.x, v2.y, v3.x, v3.y};
            const ulonglong2* bp = (const ulonglong2*)&Bs[cb][kk][tx * 8];
            ulonglong2 bv0 = bp[0], bv1 = bp[1];
            ull b2[4] = {bv0.x, bv0.y, bv1.x, bv1.y};
#pragma unroll
            for (int i = 0; i < 8; i++)
#pragma unroll
                for (int j = 0; j < 4; j++) fma2(acc[i][j], a2[i], b2[j]);
        }
        __syncthreads();
        if (more) {
#pragma unroll
            for (int l = 0; l < 2; l++) {
                float f[4] = {an[l].x, an[l].y, an[l].z, an[l].w};
#pragma unroll
                for (int q = 0; q < 4; q++) Ad[nb][akq[l] * 4 + q][arow[l]] = dup2(f[q]);
            }
        }
    }

#pragma unroll
    for (int i = 0; i < 8; i++) {
        size_t row = rowBase + ty * 8 + i;
#pragma unroll
        for (int j = 0; j < 4; j++) {
            float2 p = unpk(acc[i][j]);
#pragma unroll
            for (int s = 0; s < 2; s++) {
                int col = colBase + tx * 8 + j * 2 + s;
                float v = (s == 0) ? p.x : p.y;
                if (bias) {
                    if (gate) {
                        int n = col & 511;
                        if (n < RECN) v += bias[(col >> 9) * RECN + n];
                    } else if (col < Nvalid) {
                        v += bias[col];
                    }
                }
                C[row * NP + col] = v;
            }
        }
    }
}

// ---------------- pipelined fused GRU step ----------------
// BM=64, BN=32 (x3 gates), 256 threads, grid (16, 8).
__global__ __launch_bounds__(256)
void gru_step(const float* __restrict__ hprev,
              const float* __restrict__ xg,
              const float* __restrict__ Wt,
              const float* __restrict__ bhh,
              float* __restrict__ hout)
{
    __shared__ ull   Ad[2][16][64];      // pre-dupped h pairs (16KB)
    __shared__ float Ws[2][3][16][32];   // (12KB)
    int tid = threadIdx.x;
    int tx = tid & 15, ty = tid >> 4;
    int rowBase = blockIdx.y * 64, colBase = blockIdx.x * 32;

    ull acc[3][4];
#pragma unroll
    for (int g = 0; g < 3; g++)
#pragma unroll
        for (int i = 0; i < 4; i++) acc[g][i] = 0ULL;

    if (hprev) {
        int arow = tid >> 2, akq = tid & 3;
        int wkk = tid >> 4, wc2 = tid & 15;
        const float* Abase = hprev + (size_t)(rowBase + arow) * KPR + akq * 4;
        const float* Wbase = Wt + colBase + wc2 * 2;
        const int NT = KPR / 16;   // 31

        float4 a0 = *(const float4*)(Abase);
#pragma unroll
        for (int g = 0; g < 3; g++)
            cp8(&Ws[0][g][wkk][wc2 * 2], Wbase + (size_t)wkk * G3P + g * 512);
        cp_commit();
        {
            float f[4] = {a0.x, a0.y, a0.z, a0.w};
#pragma unroll
            for (int q = 0; q < 4; q++) Ad[0][akq * 4 + q][arow] = dup2(f[q]);
        }

        for (int kt = 0; kt < NT; kt++) {
            int cb = kt & 1, nb = (kt + 1) & 1;
            bool more = (kt + 1 < NT);
            float4 an;
            if (more) an = *(const float4*)(Abase + (kt + 1) * 16);
            cp_wait0();
            __syncthreads();
            if (more) {
#pragma unroll
                for (int g = 0; g < 3; g++)
                    cp8(&Ws[nb][g][wkk][wc2 * 2],
                        Wbase + (size_t)((kt + 1) * 16 + wkk) * G3P + g * 512);
                cp_commit();
            }
#pragma unroll
            for (int kk = 0; kk < 16; kk++) {
                const ulonglong2* ap = (const ulonglong2*)&Ad[cb][kk][ty * 4];
                ulonglong2 v0 = ap[0], v1 = ap[1];
                ull a2[4] = {v0.x, v0.y, v1.x, v1.y};
                ull w0 = *(const ull*)&Ws[cb][0][kk][tx * 2];
                ull w1 = *(const ull*)&Ws[cb][1][kk][tx * 2];
                ull w2 = *(const ull*)&Ws[cb][2][kk][tx * 2];
#pragma unroll
                for (int i = 0; i < 4; i++) {
                    fma2(acc[0][i], a2[i], w0);
                    fma2(acc[1][i], a2[i], w1);
                    fma2(acc[2][i], a2[i], w2);
                }
            }
            __syncthreads();
            if (more) {
                float f[4] = {an.x, an.y, an.z, an.w};
#pragma unroll
                for (int q = 0; q < 4; q++) Ad[nb][akq * 4 + q][arow] = dup2(f[q]);
            }
        }
    }

    // epilogue
    int col = colBase + tx * 2;
    if (col < RECN) {
        float2 bh0 = *(const float2*)(bhh + 0 * RECN + col);
        float2 bh1 = *(const float2*)(bhh + 1 * RECN + col);
        float2 bh2 = *(const float2*)(bhh + 2 * RECN + col);
#pragma unroll
        for (int i = 0; i < 4; i++) {
            int b = rowBase + ty * 4 + i;
            const float* xgb = xg + (size_t)b * G3P;
            float2 xr = *(const float2*)(xgb + 0 * 512 + col);
            float2 xz = *(const float2*)(xgb + 1 * 512 + col);
            float2 xn = *(const float2*)(xgb + 2 * 512 + col);
            float2 hr = unpk(acc[0][i]);
            float2 hz = unpk(acc[1][i]);
            float2 hn = unpk(acc[2][i]);
            float2 hp = hprev ? *(const float2*)(hprev + (size_t)b * KPR + col)
                              : make_float2(0.f, 0.f);
            float2 o;
            {
                float r = sigmf(xr.x + hr.x + bh0.x);
                float z = sigmf(xz.x + hz.x + bh1.x);
                float n = tanhfast(xn.x + r * (hn.x + bh2.x));
                o.x = (1.f - z) * n + z * hp.x;
            }
            {
                float r = sigmf(xr.y + hr.y + bh0.y);
                float z = sigmf(xz.y + hz.y + bh1.y);
                float n = tanhfast(xn.y + r * (hn.y + bh2.y));
                o.y = (1.f - z) * n + z * hp.y;
            }
            *(float2*)(hout + (size_t)b * KPR + col) = o;
        }
    }
}

// ---------------- custom GRU cell (persistent over T, one block per batch row) ----------------
__global__ __launch_bounds__(128)
void cell_all(const float* __restrict__ xg_all,   // [T*512*NCP]
              const float* __restrict__ Whh,      // [105][35]
              const float* __restrict__ bih,      // [105]
              float* __restrict__ out) {          // [512][120][35]
    __shared__ float W[NC3 * NCN];
    __shared__ float bs[NC3];
    __shared__ float h[NCN], r[NCN], u[NCN];
    __shared__ float e[64];
    int b = blockIdx.x;
    int tid = threadIdx.x;
    for (int i = tid; i < NC3 * NCN; i += 128) W[i] = Whh[i];
    if (tid < NC3) bs[tid] = bih[tid];
    if (tid < NCN) h[tid] = 0.f;
    __syncthreads();

    for (int t = 0; t < TN; t++) {
        const float* xgp = xg_all + ((size_t)t * BATCH + b) * NCP;
        if (tid < 70) {
            float s = 0.f;
#pragma unroll
            for (int k = 0; k < NCN; k++) s += h[k] * W[tid * NCN + k];
            float v = sigmf(xgp[tid] + s + bs[tid]);
            if (tid < NCN) r[tid] = v; else u[tid - NCN] = v;
        }
        __syncthreads();
        float npre = -3.0e38f;
        if (tid < NCN) {
            float s = 0.f;
#pragma unroll
            for (int k = 0; k < NCN; k++) s += r[k] * h[k] * W[(70 + tid) * NCN + k];
            npre = xgp[70 + tid] + s + bs[70 + tid];
        }
        if (tid < 64) e[tid] = (tid < NCN) ? npre : -3.0e38f;
        __syncthreads();
        if (tid < 32) {
            float v = fmaxf(e[tid], e[tid + 32]);
#pragma unroll
            for (int o = 16; o > 0; o >>= 1) v = fmaxf(v, __shfl_xor_sync(0xffffffffu, v, o));
            if (tid == 0) e[0] = v;
        }
        __syncthreads();
        float mx = e[0];
        __syncthreads();
        float ex = 0.f;
        if (tid < NCN) ex = __expf(npre - mx);
        if (tid < 64) e[tid] = (tid < NCN) ? ex : 0.f;
        __syncthreads();
        if (tid < 32) {
            float v = e[tid] + e[tid + 32];
#pragma unroll
            for (int o = 16; o > 0; o >>= 1) v += __shfl_xor_sync(0xffffffffu, v, o);
            if (tid == 0) e[0] = v;
        }
        __syncthreads();
        float sum = e[0];
        float h2 = 0.f;
        if (tid < NCN) {
            float n = ex / sum;
            h2 = (1.f - u[tid]) * n + u[tid] * h[tid];
            out[(size_t)b * (TN * NCN) + t * NCN + tid] = h2;
        }
        __syncthreads();
        if (tid < NCN) h[tid] = h2;
        __syncthreads();
    }
}

// ---------------- launch ----------------
static inline int ceil_div(int a, int b) { return (a + b - 1) / b; }

extern "C" void kernel_launch(void* const* d_in, const int* in_sizes, int n_in,
                              void* d_out, int out_size) {
    const float* z_in     = (const float*)d_in[0];
    const float* W0       = (const float*)d_in[1];
    const float* b0       = (const float*)d_in[2];
    const float* g0       = (const float*)d_in[3];
    const float* beta0    = (const float*)d_in[4];
    const float* W1       = (const float*)d_in[5];
    const float* b1       = (const float*)d_in[6];
    const float* g1       = (const float*)d_in[7];
    const float* beta1    = (const float*)d_in[8];
    const float* gru0_Wih = (const float*)d_in[9];
    const float* gru0_Whh = (const float*)d_in[10];
    const float* gru0_bih = (const float*)d_in[11];
    const float* gru0_bhh = (const float*)d_in[12];
    const float* gru1_Wih = (const float*)d_in[13];
    const float* gru1_Whh = (const float*)d_in[14];
    const float* gru1_bih = (const float*)d_in[15];
    const float* gru1_bhh = (const float*)d_in[16];
    const float* cell_Wih = (const float*)d_in[17];
    const float* cell_Whh = (const float*)d_in[18];
    const float* cell_bih = (const float*)d_in[19];
    float* out = (float*)d_out;

    float *z1, *z2, *xg0, *X0, *XG1, *X1, *XGc;
    float *WtD0, *WtD1, *Wt0x, *Wt0h, *Wt1x, *Wt1h, *Wtc;
    cudaGetSymbolAddress((void**)&z1,  g_z1);
    cudaGetSymbolAddress((void**)&z2,  g_z2);
    cudaGetSymbolAddress((void**)&xg0, g_xg0);
    cudaGetSymbolAddress((void**)&X0,  g_X0);
    cudaGetSymbolAddress((void**)&XG1, g_XG1);
    cudaGetSymbolAddress((void**)&X1,  g_X1);
    cudaGetSymbolAddress((void**)&XGc, g_XGc);
    cudaGetSymbolAddress((void**)&WtD0, g_WtD0);
    cudaGetSymbolAddress((void**)&WtD1, g_WtD1);
    cudaGetSymbolAddress((void**)&Wt0x, g_Wt0x);
    cudaGetSymbolAddress((void**)&Wt0h, g_Wt0h);
    cudaGetSymbolAddress((void**)&Wt1x, g_Wt1x);
    cudaGetSymbolAddress((void**)&Wt1h, g_Wt1h);
    cudaGetSymbolAddress((void**)&Wtc,  g_Wtc);

    // L0: all transposes in one launch
    trans_all<<<dim3(48, 16, 7), dim3(32, 8)>>>(
        W0, W1, gru0_Wih, gru0_Whh, gru1_Wih, gru1_Whh, cell_Wih,
        WtD0, WtD1, Wt0x, Wt0h, Wt1x, Wt1h, Wtc);

    // L1, L2: dense + BN
    gemm_naive<<<dim3(ceil_div(HIDN,128), BATCH/128), 256>>>(
        z_in, WtD0, b0, g0, beta0, z1, BATCH, HIDN, HIDN, HIDN);
    gemm_naive<<<dim3(ceil_div(HIDN,128), BATCH/128), 256>>>(
        z1, WtD1, b1, g1, beta1, z2, BATCH, HIDN, HIDN, KPH);

    // L3: GRU0 input gates (time-invariant), padded output [512][G3P]
    gemmP<<<dim3(G3P/128, BATCH/128), 256>>>(
        z2, KPH, KPH, Wt0x, G3P, gru0_bih, 1, RECN, xg0);

    // L4..: GRU0 recurrence (L5 = gru_step t=1, full k-loop -> profiled by ncu)
    dim3 gsGrid(16, BATCH / 64);
    for (int t = 0; t < TN; t++) {
        const float* hp = (t == 0) ? nullptr : (X0 + (size_t)(t - 1) * BHP);
        gru_step<<<gsGrid, 256>>>(hp, xg0, Wt0h, gru0_bhh, X0 + (size_t)t * BHP);
    }

    // GRU1 input gates for all T at once
    gemmP<<<dim3(G3P/128, (TN * BATCH) / 128), 256>>>(
        X0, KPR, KPR, Wt1x, G3P, gru1_bih, 1, RECN, XG1);

    // GRU1 recurrence
    for (int t = 0; t < TN; t++) {
        const float* hp = (t == 0) ? nullptr : (X1 + (size_t)(t - 1) * BHP);
        gru_step<<<gsGrid, 256>>>(hp, XG1 + (size_t)t * BGP, Wt1h, gru1_bhh,
                                  X1 + (size_t)t * BHP);
    }

    // cell input gates for all T (no bias), padded output stride NCP
    gemmP<<<dim3(NCP/128, (TN * BATCH) / 128), 256>>>(
        X1, KPR, KPR, Wtc, NCP, nullptr, 0, NC3, XGc);

    // custom cell recurrence
    cell_all<<<BATCH, 128>>>(XGc, cell_Whh, cell_bih, out);
}